// round 8
// baseline (speedup 1.0000x reference)
#include <cuda_runtime.h>
#include <math.h>
#include <float.h>

// GaussianQuantRegularizer2 — fused codebook argmax + KL mean, single kernel.
// R7: single-chain packed accumulation — smem entry (gA_t,gB_t) as u64[16]
// lets one 16-FFMA2 chain produce (scoreA,scoreB) packed: drops the fadd2
// horizontal and one fmul2 per pair-row (fma floor -6%, issue -10%).
//
// Identities: zhat == prior[idx] (STE cancels), kl_loss == mean(kl2)
// (ge+eq+le==1), argmax score == 16-dim dot f=[iv-1, mu*iv] . g_k=[-s^2/2, s].

#define THREADS 256
#define NPAIRS  512            // 1024 codes as 512 (even,odd) code-pairs
#define NB      256            // 65536 row-pairs / 256 threads
#define SMEM_ENT (NPAIRS * 16 + 16)  // u64 entries; +16 pad for tail prefetch
#define SMEM_BYTES (SMEM_ENT * 8)    // 65664

__device__ float g_partials[NB];
__device__ unsigned int g_done = 0;

static __device__ __forceinline__ unsigned long long pack2f(float lo, float hi) {
    unsigned long long r;
    asm("mov.b64 %0, {%1, %2};" : "=l"(r) : "f"(lo), "f"(hi));
    return r;
}
static __device__ __forceinline__ void unpack2f(unsigned long long v, float &lo, float &hi) {
    asm("mov.b64 {%0, %1}, %2;" : "=f"(lo), "=f"(hi) : "l"(v));
}
static __device__ __forceinline__ unsigned long long ffma2(unsigned long long a,
                                                           unsigned long long b,
                                                           unsigned long long c) {
    unsigned long long d;
    asm("fma.rn.f32x2 %0, %1, %2, %3;" : "=l"(d) : "l"(a), "l"(b), "l"(c));
    return d;
}
static __device__ __forceinline__ unsigned long long fmul2(unsigned long long a,
                                                           unsigned long long b) {
    unsigned long long d;
    asm("mul.rn.f32x2 %0, %1, %2;" : "=l"(d) : "l"(a), "l"(b));
    return d;
}

__global__ __launch_bounds__(THREADS, 2)
void gqr_main(const float* __restrict__ z, const float* __restrict__ prior,
              float* __restrict__ out, int nrows, long long idx_off,
              long long kl_off, float scale)
{
    // Codebook as u64 stream: entry (16*p + t) = (gA_t, gB_t) for code pair p,
    // feature t (0..7 quadratic -s^2/2, 8..15 linear s). A=code 2p, B=2p+1.
    extern __shared__ unsigned long long cbu[];

    for (int e = threadIdx.x; e < NPAIRS * 16; e += THREADS) {
        int p = e >> 4, t = e & 15;
        int k0 = p * 2, k1 = k0 + 1;
        float a, b;
        if (t < 8) {
            float x = prior[k0 * 8 + t]; a = -0.5f * x * x;
            float y = prior[k1 * 8 + t]; b = -0.5f * y * y;
        } else {
            a = prior[k0 * 8 + t - 8];
            b = prior[k1 * 8 + t - 8];
        }
        cbu[e] = pack2f(a, b);
    }
    if (threadIdx.x < 16) cbu[NPAIRS * 16 + threadIdx.x] = 0ULL;  // prefetch pad
    __syncthreads();

    int tt = blockIdx.x * THREADS + threadIdx.x;   // one row-PAIR per thread
    int npr = nrows >> 1;
    float klacc = 0.0f;

    if (tt < npr) {
        int n0 = tt << 1;
        int bb = n0 >> 12;          // H*W = 4096
        int hw = n0 & 4095;         // even -> rows n0, n0+1 share bb
        const float* zp = z + ((size_t)bb << 16) + hw;

        unsigned long long fp[2][16];   // fp[r][t] = (f_t, f_t)
        #pragma unroll
        for (int d = 0; d < 8; d++) {
            float2 mu2 = *(const float2*)(zp + ((size_t)d << 12));
            float2 lv2 = *(const float2*)(zp + ((size_t)(8 + d) << 12));
            #pragma unroll
            for (int r = 0; r < 2; r++) {
                float mu = r ? mu2.y : mu2.x;
                float lv = r ? lv2.y : lv2.x;
                lv = fminf(fmaxf(lv, -30.0f), 20.0f);
                float var = expf(lv);
                float iv  = 1.0f / var;
                fp[r][d]     = pack2f(iv - 1.0f, iv - 1.0f);
                float fl  = mu * iv;
                fp[r][8 + d] = pack2f(fl, fl);
                klacc += mu * mu + var - 1.0f - lv;
            }
        }

        float bestE[2] = { -FLT_MAX, -FLT_MAX };
        float bestO[2] = { -FLT_MAX, -FLT_MAX };
        int   pE[2] = { 0, 0 }, pO[2] = { 0, 0 };

        // double-buffered prefetch: q[buf] computes while q[buf^1] loads next
        ulonglong2 q[2][8];
        const ulonglong2* cp = (const ulonglong2*)cbu;
        #pragma unroll
        for (int jj = 0; jj < 8; jj++) q[0][jj] = cp[jj];

        #define GQR_STEP(BUF, POFF)                                            \
        do {                                                                   \
            _Pragma("unroll")                                                  \
            for (int jj = 0; jj < 8; jj++)                                     \
                q[(BUF) ^ 1][jj] = cp[8 * ((POFF) + 1) + jj];                  \
            const unsigned long long* qq = (const unsigned long long*)q[BUF];  \
            _Pragma("unroll")                                                  \
            for (int r = 0; r < 2; r++) {                                      \
                unsigned long long acc = fmul2(fp[r][0], qq[0]);               \
                _Pragma("unroll")                                              \
                for (int t = 1; t < 16; t++)                                   \
                    acc = ffma2(fp[r][t], qq[t], acc);                         \
                float sE, sO;                                                  \
                unpack2f(acc, sE, sO);                                         \
                bool g0 = sE > bestE[r];                                       \
                bool g1 = sO > bestO[r];                                       \
                bestE[r] = fmaxf(bestE[r], sE);                                \
                bestO[r] = fmaxf(bestO[r], sO);                                \
                pE[r] = g0 ? (p + (POFF)) : pE[r];                             \
                pO[r] = g1 ? (p + (POFF)) : pO[r];                             \
            }                                                                  \
        } while (0)

        for (int p = 0; p < NPAIRS; p += 2) {
            GQR_STEP(0, 0);
            GQR_STEP(1, 1);
            cp += 16;
        }
        #undef GQR_STEP

        int idx[2];
        #pragma unroll
        for (int r = 0; r < 2; r++) {
            int ie = 2 * pE[r], io = 2 * pO[r] + 1;
            if (bestO[r] > bestE[r])      idx[r] = io;
            else if (bestO[r] < bestE[r]) idx[r] = ie;
            else                          idx[r] = min(ie, io);  // first-max tie
        }

        const float* pvA = prior + (size_t)idx[0] * 8;
        const float* pvB = prior + (size_t)idx[1] * 8;
        #pragma unroll
        for (int d = 0; d < 8; d++) {
            float2 o; o.x = pvA[d]; o.y = pvB[d];
            *(float2*)(out + (((size_t)(bb * 8 + d)) << 12) + hw) = o;
        }
        out[idx_off + n0]     = (float)idx[0];
        out[idx_off + n0 + 1] = (float)idx[1];
    }

    // deterministic block-level KL partial
    #pragma unroll
    for (int o = 16; o > 0; o >>= 1)
        klacc += __shfl_down_sync(0xFFFFFFFFu, klacc, o);
    __shared__ float red[THREADS / 32];
    __shared__ int last_flag;
    if ((threadIdx.x & 31) == 0) red[threadIdx.x >> 5] = klacc;
    __syncthreads();
    if (threadIdx.x == 0) {
        float s = 0.0f;
        #pragma unroll
        for (int i = 0; i < THREADS / 32; i++) s += red[i];
        g_partials[blockIdx.x] = s;
        __threadfence();
        unsigned int old = atomicAdd(&g_done, 1u);
        last_flag = (old == (unsigned int)(NB - 1)) ? 1 : 0;
    }
    __syncthreads();

    // last block fuses the finalize: sums partials, writes kl, resets counter
    if (last_flag) {
        __threadfence();
        float s = 0.0f;
        for (int i = threadIdx.x; i < NB; i += THREADS) s += g_partials[i];
        #pragma unroll
        for (int o = 16; o > 0; o >>= 1)
            s += __shfl_down_sync(0xFFFFFFFFu, s, o);
        if ((threadIdx.x & 31) == 0) red[threadIdx.x >> 5] = s;
        __syncthreads();
        if (threadIdx.x == 0) {
            float acc = 0.0f;
            #pragma unroll
            for (int i = 0; i < THREADS / 32; i++) acc += red[i];
            out[kl_off] = acc * scale;
            g_done = 0;                 // reset for next graph replay
            __threadfence();
        }
    }
}

extern "C" void kernel_launch(void* const* d_in, const int* in_sizes, int n_in,
                              void* d_out, int out_size)
{
    const float* z     = (const float*)d_in[0];
    // d_in[1] (noise) is provably unused by the forward values.
    const float* prior = (const float*)d_in[2];
    float* out = (float*)d_out;

    int nrows = in_sizes[0] / 16;                       // 131072
    long long idx_off = (long long)out_size - (long long)nrows;
    if (idx_off < 1) idx_off = 1;
    long long kl_off  = idx_off - 1;

    float scale = (1.4426f * 0.5f) / (float)nrows;

    (void)cudaFuncSetAttribute(gqr_main,
                               cudaFuncAttributeMaxDynamicSharedMemorySize, SMEM_BYTES);
    gqr_main<<<NB, THREADS, SMEM_BYTES>>>(z, prior, out, nrows, idx_off,
                                          kl_off, scale);
}